// round 10
// baseline (speedup 1.0000x reference)
#include <cuda_runtime.h>
#include <cuda_bf16.h>

// Problem constants (fixed by the dataset instance)
#define N1TOT 65536
#define N2TOT 16384
#define N1PB  16384
#define N2PB  4096
#define CV    192   // Cout*3
#define G     8      // bins per axis
#define NBIN  512    // per batch
#define NBINT 2048   // total (4 batches)
#define BINW  0.125f

// Scratch
__device__ float  g_y2t[N2TOT * CV];   // y2 point-major [n][c*3+v]
__device__ int    g_cnt2[NBINT];
__device__ int    g_start2[NBINT + 1];
__device__ float4 g_b2[N2TOT];
__device__ int    g_cnt1[NBINT];
__device__ int    g_start1[NBINT + 1];
__device__ float4 g_b1[N1TOT];
__device__ float  g_kd[3][N1TOT];
__device__ int    g_ki[3][N1TOT];

// ---- tf32 helpers ---------------------------------------------------------
__device__ __forceinline__ unsigned tf32_rna(float v) {
    unsigned r; asm("cvt.rna.tf32.f32 %0, %1;" : "=r"(r) : "f"(v)); return r;
}
__device__ __forceinline__ void mma_tf32(
    float& c0, float& c1, float& c2, float& c3,
    unsigned a0, unsigned a1, unsigned a2, unsigned a3,
    unsigned b0, unsigned b1)
{
    asm("mma.sync.aligned.m16n8k8.row.col.f32.tf32.tf32.f32 "
        "{%0,%1,%2,%3}, {%4,%5,%6,%7}, {%8,%9}, {%0,%1,%2,%3};"
        : "+f"(c0), "+f"(c1), "+f"(c2), "+f"(c3)
        : "r"(a0), "r"(a1), "r"(a2), "r"(a3), "r"(b0), "r"(b1));
}

// ---------------------------------------------------------------------------
// Fused VN linear+leakyrelu, tensor-core 3xTF32.
//   blocks [0,512)    : layer2 (x2, CIN=128, N=16384) -> g_y2t point-major
//   blocks [512,2560) : layer1 (x1, CIN=64,  N=65536) -> out channel-major
// Block: 256 thr = 8 warps, 32-point tile, 64 out channels.
//   warp w: channels [16*(w&3), +16), points [16*(w>>2), +16)  (2 n8 tiles)
// K chunked by 32; W (f,d) and X staged in smem pre-split into tf32 hi/lo.
// A = W[o][k] stride 36 (conflict-free); B = X[k][pt] stride 40 per v.
// Accumulators accP/accD[v][s][4] -> nonlinearity fully register-local.
// ---------------------------------------------------------------------------
#define WFH 0
#define WFL 2304
#define WDH 4608
#define WDL 6912
#define XH  9216          // + v*1280
#define XL  13056
#define SMW 16896         // total smem words (67584 B)

__global__ void __launch_bounds__(256) vn_fused_kernel(
    const float* __restrict__ x1, const float* __restrict__ w1f,
    const float* __restrict__ w1d,
    const float* __restrict__ x2, const float* __restrict__ w2f,
    const float* __restrict__ w2d,
    float* __restrict__ out)
{
    extern __shared__ unsigned swu[];
    const int tid = threadIdx.x;
    const int lane = tid & 31;
    const int w   = tid >> 5;
    const int g   = lane >> 2;        // 0..7
    const int tig = lane & 3;         // 0..3
    const int ch_base = (w & 3) * 16;
    const int n_base  = (w >> 2) * 16;

    const bool is2 = blockIdx.x < 512;
    const float* x  = is2 ? x2  : x1;
    const float* wf = is2 ? w2f : w1f;
    const float* wd = is2 ? w2d : w1d;
    const int CIN = is2 ? 128 : 64;
    const int N   = is2 ? N2TOT : N1TOT;
    const int n0  = (is2 ? blockIdx.x : blockIdx.x - 512) * 32;

    float accP[3][2][4], accD[3][2][4];
#pragma unroll
    for (int v = 0; v < 3; v++)
#pragma unroll
        for (int s = 0; s < 2; s++)
#pragma unroll
            for (int j = 0; j < 4; j++) { accP[v][s][j] = 0.f; accD[v][s][j] = 0.f; }

    for (int c0 = 0; c0 < CIN; c0 += 32) {
        __syncthreads();
        // stage W chunk (f and d), split hi/lo.  i -> (o = i>>5, cc = i&31)
        for (int i = tid; i < 2048; i += 256) {
            int o = i >> 5, cc = i & 31;
            float vf = wf[o * CIN + c0 + cc];
            float vd = wd[o * CIN + c0 + cc];
            unsigned fh = tf32_rna(vf);
            unsigned dh = tf32_rna(vd);
            swu[WFH + o * 36 + cc] = fh;
            swu[WDH + o * 36 + cc] = dh;
            swu[WFL + o * 36 + cc] = tf32_rna(vf - __uint_as_float(fh));
            swu[WDL + o * 36 + cc] = tf32_rna(vd - __uint_as_float(dh));
        }
        // stage X chunk, split hi/lo.  i -> (v = i>>10, cc = (i>>5)&31, pp = i&31)
        for (int i = tid; i < 3072; i += 256) {
            int v = i >> 10, cc = (i >> 5) & 31, pp = i & 31;
            float xv = x[(size_t)(c0 + cc) * 3 * N + (size_t)v * N + (n0 + pp)];
            unsigned xh = tf32_rna(xv);
            swu[XH + v * 1280 + cc * 40 + pp] = xh;
            swu[XL + v * 1280 + cc * 40 + pp] = tf32_rna(xv - __uint_as_float(xh));
        }
        __syncthreads();

#pragma unroll
        for (int kk = 0; kk < 4; kk++) {
            const int k0 = kk * 8;
            const int r0 = (ch_base + g) * 36 + k0 + tig;
            const int r1 = r0 + 8 * 36;
            unsigned afh0 = swu[WFH + r0], afh1 = swu[WFH + r1];
            unsigned afh2 = swu[WFH + r0 + 4], afh3 = swu[WFH + r1 + 4];
            unsigned afl0 = swu[WFL + r0], afl1 = swu[WFL + r1];
            unsigned afl2 = swu[WFL + r0 + 4], afl3 = swu[WFL + r1 + 4];
            unsigned adh0 = swu[WDH + r0], adh1 = swu[WDH + r1];
            unsigned adh2 = swu[WDH + r0 + 4], adh3 = swu[WDH + r1 + 4];
            unsigned adl0 = swu[WDL + r0], adl1 = swu[WDL + r1];
            unsigned adl2 = swu[WDL + r0 + 4], adl3 = swu[WDL + r1 + 4];
#pragma unroll
            for (int v = 0; v < 3; v++) {
#pragma unroll
                for (int s = 0; s < 2; s++) {
                    const int col = n_base + s * 8 + g;
                    const int bidx = v * 1280 + (k0 + tig) * 40 + col;
                    unsigned bh0 = swu[XH + bidx];
                    unsigned bh1 = swu[XH + bidx + 4 * 40];
                    unsigned bl0 = swu[XL + bidx];
                    unsigned bl1 = swu[XL + bidx + 4 * 40];
                    float* cP = accP[v][s];
                    float* cD = accD[v][s];
                    mma_tf32(cP[0], cP[1], cP[2], cP[3], afh0, afh1, afh2, afh3, bh0, bh1);
                    mma_tf32(cP[0], cP[1], cP[2], cP[3], afl0, afl1, afl2, afl3, bh0, bh1);
                    mma_tf32(cP[0], cP[1], cP[2], cP[3], afh0, afh1, afh2, afh3, bl0, bl1);
                    mma_tf32(cD[0], cD[1], cD[2], cD[3], adh0, adh1, adh2, adh3, bh0, bh1);
                    mma_tf32(cD[0], cD[1], cD[2], cD[3], adl0, adl1, adl2, adl3, bh0, bh1);
                    mma_tf32(cD[0], cD[1], cD[2], cD[3], adh0, adh1, adh2, adh3, bl0, bl1);
                }
            }
        }
    }

    // nonlinearity + writeback
    if (!is2) {
#pragma unroll
        for (int s = 0; s < 2; s++) {
            float vals[4][3];
#pragma unroll
            for (int j = 0; j < 4; j++) {
                float P0 = accP[0][s][j], P1 = accP[1][s][j], P2 = accP[2][s][j];
                float D0 = accD[0][s][j], D1 = accD[1][s][j], D2 = accD[2][s][j];
                float dot = P0 * D0 + P1 * D1 + P2 * D2;
                float dd  = D0 * D0 + D1 * D1 + D2 * D2;
                float coef = (dot < 0.f) ? (0.8f * dot / (dd + 1e-6f)) : 0.f;
                vals[j][0] = P0 - coef * D0;
                vals[j][1] = P1 - coef * D1;
                vals[j][2] = P2 - coef * D2;
            }
            const int n_g = n0 + n_base + s * 8 + 2 * tig;
#pragma unroll
            for (int h = 0; h < 2; h++) {
                const int o = ch_base + g + h * 8;
#pragma unroll
                for (int v = 0; v < 3; v++) {
                    float2 st = make_float2(vals[h * 2][v], vals[h * 2 + 1][v]);
                    *(float2*)&out[(size_t)(o * 3 + v) * N + n_g] = st;
                }
            }
        }
    } else {
        __syncthreads();                 // smem now reusable as transpose buf
        float* tb = (float*)swu;         // [32][193]
#pragma unroll
        for (int s = 0; s < 2; s++) {
#pragma unroll
            for (int j = 0; j < 4; j++) {
                float P0 = accP[0][s][j], P1 = accP[1][s][j], P2 = accP[2][s][j];
                float D0 = accD[0][s][j], D1 = accD[1][s][j], D2 = accD[2][s][j];
                float dot = P0 * D0 + P1 * D1 + P2 * D2;
                float dd  = D0 * D0 + D1 * D1 + D2 * D2;
                float coef = (dot < 0.f) ? (0.8f * dot / (dd + 1e-6f)) : 0.f;
                const int pl = n_base + s * 8 + 2 * tig + (j & 1);
                const int o  = ch_base + g + ((j >> 1) << 3);
                tb[pl * 193 + o * 3 + 0] = P0 - coef * D0;
                tb[pl * 193 + o * 3 + 1] = P1 - coef * D1;
                tb[pl * 193 + o * 3 + 2] = P2 - coef * D2;
            }
        }
        __syncthreads();
        for (int i = tid; i < 32 * CV; i += 256) {
            int pp = i / CV, cv = i - pp * CV;
            g_y2t[(size_t)(n0 + pp) * CV + cv] = tb[pp * 193 + cv];
        }
    }
}

// ---------------------------------------------------------------------------
// Spatial binning build (unchanged from R9): zero -> count -> prefix -> scatter
// ---------------------------------------------------------------------------
__device__ __forceinline__ int bin_of(int batch, float x, float y, float z) {
    int bx = min(G - 1, max(0, (int)(x * 8.0f)));
    int by = min(G - 1, max(0, (int)(y * 8.0f)));
    int bz = min(G - 1, max(0, (int)(z * 8.0f)));
    return batch * NBIN + (bz * G + by) * G + bx;
}

__global__ void zero_kernel() {
    int t = blockIdx.x * 256 + threadIdx.x;
    if (t < NBINT) g_cnt2[t] = 0;
    else if (t < 2 * NBINT) g_cnt1[t - NBINT] = 0;
}

__global__ void bin_count_kernel(const float* __restrict__ p1,
                                 const float* __restrict__ p2) {
    int t = blockIdx.x * 256 + threadIdx.x;
    if (t < N2TOT) {
        float x = p2[3 * t], y = p2[3 * t + 1], z = p2[3 * t + 2];
        atomicAdd(&g_cnt2[bin_of(t >> 12, x, y, z)], 1);
    } else {
        int i = t - N2TOT;
        float x = p1[3 * i], y = p1[3 * i + 1], z = p1[3 * i + 2];
        atomicAdd(&g_cnt1[bin_of(i >> 14, x, y, z)], 1);
    }
}

__global__ void prefix_kernel() {
    int* cnt   = blockIdx.x ? g_cnt1 : g_cnt2;
    int* start = blockIdx.x ? g_start1 : g_start2;
    __shared__ int wsum[8];
    int tid = threadIdx.x;
    int loc[8]; int sum = 0;
#pragma unroll
    for (int k = 0; k < 8; k++) { loc[k] = cnt[tid * 8 + k]; sum += loc[k]; }
    int lane = tid & 31, wid = tid >> 5;
    int v = sum;
#pragma unroll
    for (int o = 1; o < 32; o <<= 1) {
        int t2 = __shfl_up_sync(0xffffffffu, v, o);
        if (lane >= o) v += t2;
    }
    if (lane == 31) wsum[wid] = v;
    __syncthreads();
    int woff = 0;
    for (int k = 0; k < wid; k++) woff += wsum[k];
    int excl = woff + v - sum;
#pragma unroll
    for (int k = 0; k < 8; k++) {
        start[tid * 8 + k] = excl;
        cnt[tid * 8 + k] = excl;
        excl += loc[k];
    }
    if (tid == 255) start[NBINT] = excl;
}

__global__ void bin_scatter_kernel(const float* __restrict__ p1,
                                   const float* __restrict__ p2) {
    int t = blockIdx.x * 256 + threadIdx.x;
    if (t < N2TOT) {
        float x = p2[3 * t], y = p2[3 * t + 1], z = p2[3 * t + 2];
        int pos = atomicAdd(&g_cnt2[bin_of(t >> 12, x, y, z)], 1);
        g_b2[pos] = make_float4(x, y, z, __int_as_float(t & (N2PB - 1)));
    } else {
        int i = t - N2TOT;
        float x = p1[3 * i], y = p1[3 * i + 1], z = p1[3 * i + 2];
        int pos = atomicAdd(&g_cnt1[bin_of(i >> 14, x, y, z)], 1);
        g_b1[pos] = make_float4(x, y, z, __int_as_float(i));
    }
}

// ---------------------------------------------------------------------------
// 3-NN via bins (unchanged from R9): 3x3x3 scan + margin test + exact fallback
// ---------------------------------------------------------------------------
__global__ void __launch_bounds__(256) knn_bin_kernel()
{
    const int t = blockIdx.x * 256 + threadIdx.x;
    float4 q = g_b1[t];
    const int batch = t >> 14;
    const int orig  = __float_as_int(q.w);
    const float qx = q.x, qy = q.y, qz = q.z;
    int bx = min(G - 1, max(0, (int)(qx * 8.0f)));
    int by = min(G - 1, max(0, (int)(qy * 8.0f)));
    int bz = min(G - 1, max(0, (int)(qz * 8.0f)));

    float a0 = 3.4e38f, a1 = 3.4e38f, a2 = 3.4e38f;
    int   i0 = 0, i1 = 0, i2 = 0;

    const int xlo = max(bx - 1, 0), xhi = min(bx + 1, G - 1);
    const int ylo = max(by - 1, 0), yhi = min(by + 1, G - 1);
    const int zlo = max(bz - 1, 0), zhi = min(bz + 1, G - 1);
    const int base = batch * NBIN;

    for (int z = zlo; z <= zhi; z++) {
        for (int y = ylo; y <= yhi; y++) {
            int b0 = base + (z * G + y) * G + xlo;
            int s = g_start2[b0];
            int e = g_start2[b0 + (xhi - xlo) + 1];
            for (int j = s; j < e; j++) {
                float4 c = g_b2[j];
                float dx = qx - c.x, dy = qy - c.y, dz = qz - c.z;
                float d2 = fmaf(dx, dx, fmaf(dy, dy, dz * dz));
                int idx = __float_as_int(c.w);
                bool c0 = d2 < a0, c1 = d2 < a1, c2 = d2 < a2;
                a2 = c1 ? a1 : (c2 ? d2 : a2);  i2 = c1 ? i1 : (c2 ? idx : i2);
                a1 = c0 ? a0 : (c1 ? d2 : a1);  i1 = c0 ? i0 : (c1 ? idx : i1);
                a0 = c0 ? d2 : a0;              i0 = c0 ? idx : i0;
            }
        }
    }

    float margin = 3.4e38f;
    if (bx >= 2)     margin = fminf(margin, qx - (bx - 1) * BINW);
    if (bx <= G - 3) margin = fminf(margin, (bx + 2) * BINW - qx);
    if (by >= 2)     margin = fminf(margin, qy - (by - 1) * BINW);
    if (by <= G - 3) margin = fminf(margin, (by + 2) * BINW - qy);
    if (bz >= 2)     margin = fminf(margin, qz - (bz - 1) * BINW);
    if (bz <= G - 3) margin = fminf(margin, (bz + 2) * BINW - qz);

    if (a2 > margin * margin) {
        a0 = a1 = a2 = 3.4e38f; i0 = i1 = i2 = 0;
        int s = batch * N2PB, e = s + N2PB;
#pragma unroll 1
        for (int j = s; j < e; j++) {
            float4 c = g_b2[j];
            float dx = qx - c.x, dy = qy - c.y, dz = qz - c.z;
            float d2 = fmaf(dx, dx, fmaf(dy, dy, dz * dz));
            int idx = __float_as_int(c.w);
            bool c0 = d2 < a0, c1 = d2 < a1, c2 = d2 < a2;
            a2 = c1 ? a1 : (c2 ? d2 : a2);  i2 = c1 ? i1 : (c2 ? idx : i2);
            a1 = c0 ? a0 : (c1 ? d2 : a1);  i1 = c0 ? i0 : (c1 ? idx : i1);
            a0 = c0 ? d2 : a0;              i0 = c0 ? idx : i0;
        }
    }

    g_kd[0][orig] = a0; g_ki[0][orig] = i0;
    g_kd[1][orig] = a1; g_ki[1][orig] = i1;
    g_kd[2][orig] = a2; g_ki[2][orig] = i2;
}

// ---------------------------------------------------------------------------
// Interp weights + gather + RMW into out (coalesced over queries).
// ---------------------------------------------------------------------------
__global__ void __launch_bounds__(256) interp_kernel(float* __restrict__ out)
{
    const int ng = blockIdx.x * 256 + threadIdx.x;
    const int batch = ng >> 14;

    float a0 = g_kd[0][ng], a1 = g_kd[1][ng], a2 = g_kd[2][ng];
    int   i0 = g_ki[0][ng], i1 = g_ki[1][ng], i2 = g_ki[2][ng];

    float w0 = 1.f / (a0 + 1e-8f);
    float w1 = 1.f / (a1 + 1e-8f);
    float w2 = 1.f / (a2 + 1e-8f);
    float inv = 1.f / (w0 + w1 + w2);
    w0 *= inv; w1 *= inv; w2 *= inv;

    const float4* f0 = (const float4*)(g_y2t + (size_t)(batch * N2PB + i0) * CV);
    const float4* f1 = (const float4*)(g_y2t + (size_t)(batch * N2PB + i1) * CV);
    const float4* f2 = (const float4*)(g_y2t + (size_t)(batch * N2PB + i2) * CV);
    float* op = out + ng;

#pragma unroll 4
    for (int c4 = 0; c4 < CV / 4; c4++) {
        float4 a = f0[c4], b = f1[c4], c = f2[c4];
        op[(size_t)(4 * c4 + 0) * N1TOT] += w0 * a.x + w1 * b.x + w2 * c.x;
        op[(size_t)(4 * c4 + 1) * N1TOT] += w0 * a.y + w1 * b.y + w2 * c.y;
        op[(size_t)(4 * c4 + 2) * N1TOT] += w0 * a.z + w1 * b.z + w2 * c.z;
        op[(size_t)(4 * c4 + 3) * N1TOT] += w0 * a.w + w1 * b.w + w2 * c.w;
    }
}

// ---------------------------------------------------------------------------
extern "C" void kernel_launch(void* const* d_in, const int* in_sizes, int n_in,
                              void* d_out, int out_size)
{
    const float* p1  = (const float*)d_in[0];
    const float* x1  = (const float*)d_in[1];
    const float* p2  = (const float*)d_in[3];
    const float* x2  = (const float*)d_in[4];
    const float* w1f = (const float*)d_in[6];
    const float* w1d = (const float*)d_in[7];
    const float* w2f = (const float*)d_in[8];
    const float* w2d = (const float*)d_in[9];
    float* out = (float*)d_out;

    const int SVN = SMW * 4;   // 67584 B

    cudaFuncSetAttribute((const void*)vn_fused_kernel,
                         cudaFuncAttributeMaxDynamicSharedMemorySize, SVN);

    // VN layers (tensor-core 3xTF32): [0,512): y2 ; [512,2560): y1
    vn_fused_kernel<<<2560, 256, SVN>>>(x1, w1f, w1d, x2, w2f, w2d, out);

    // Spatial bin build (p1 and p2)
    zero_kernel<<<16, 256>>>();
    bin_count_kernel<<<(N2TOT + N1TOT) / 256, 256>>>(p1, p2);
    prefix_kernel<<<2, 256>>>();
    bin_scatter_kernel<<<(N2TOT + N1TOT) / 256, 256>>>(p1, p2);

    // 3-NN via bins (bin-sorted queries)
    knn_bin_kernel<<<N1TOT / 256, 256>>>();

    // interpolation + add into out
    interp_kernel<<<N1TOT / 256, 256>>>(out);
}

// round 11
// speedup vs baseline: 1.3645x; 1.3645x over previous
#include <cuda_runtime.h>
#include <cuda_bf16.h>

// Problem constants (fixed by the dataset instance)
#define N1TOT 65536
#define N2TOT 16384
#define N1PB  16384
#define N2PB  4096
#define CV    192   // Cout*3
#define G     8      // bins per axis
#define NBIN  512    // per batch
#define NBINT 2048   // total (4 batches)
#define BINW  0.125f

typedef unsigned long long ull;

// Scratch
__device__ float  g_y2t[N2TOT * CV];   // y2 point-major [n][c*3+v]
__device__ int    g_cnt2[NBINT];
__device__ int    g_start2[NBINT + 1];
__device__ float4 g_b2[N2TOT];
__device__ int    g_cnt1[NBINT];
__device__ int    g_start1[NBINT + 1];
__device__ float4 g_b1[N1TOT];
__device__ float  g_kd[3][N1TOT];
__device__ int    g_ki[3][N1TOT];

// ---- packed fp32x2 helpers (Blackwell) ------------------------------------
__device__ __forceinline__ ull f2fma(ull a, ull b, ull c) {
    ull d; asm("fma.rn.f32x2 %0, %1, %2, %3;" : "=l"(d) : "l"(a), "l"(b), "l"(c));
    return d;
}
__device__ __forceinline__ void f2unpack(ull p, float& lo, float& hi) {
    asm("mov.b64 {%0, %1}, %2;" : "=f"(lo), "=f"(hi) : "l"(p));
}

// ---------------------------------------------------------------------------
// Fused VN linear+leakyrelu for BOTH layers in one launch (f32x2 path, R9),
// now SOFTWARE-PIPELINED: chunk c+1's global loads are prefetched into
// registers during chunk c's compute, so the per-chunk critical path is
// sync -> STS -> sync -> compute with no exposed global latency.
//   blocks [0,512)    : layer2 (x2, CIN=128, N=16384) -> g_y2t point-major
//   blocks [512,2560) : layer1 (x1, CIN=64,  N=65536) -> out channel-major
// ---------------------------------------------------------------------------
#define WS2 66   // float2 stride per channel row

__global__ void __launch_bounds__(256, 2) vn_fused_kernel(
    const float* __restrict__ x1, const float* __restrict__ w1f,
    const float* __restrict__ w1d,
    const float* __restrict__ x2, const float* __restrict__ w2f,
    const float* __restrict__ w2d,
    float* __restrict__ out)
{
    extern __shared__ float sm[];
    ull* ws = (ull*)sm;               // [32][WS2]  (wf,wd) pairs
    ull* xs = ws + 32 * WS2;          // [32][3][32] (x,x) dup pairs
    float2* wsf2 = (float2*)ws;
    float2* xsf2 = (float2*)xs;

    const int tid = threadIdx.x;
    const int p  = tid & 31;
    const int og = tid >> 5;
    const bool is2 = blockIdx.x < 512;
    const float* x  = is2 ? x2  : x1;
    const float* wf = is2 ? w2f : w1f;
    const float* wd = is2 ? w2d : w1d;
    const int CIN = is2 ? 128 : 64;
    const int N   = is2 ? N2TOT : N1TOT;
    const int n0  = (is2 ? blockIdx.x : blockIdx.x - 512) * 32;

    ull pd[8][3];
#pragma unroll
    for (int i = 0; i < 8; i++)
#pragma unroll
        for (int v = 0; v < 3; v++) pd[i][v] = 0ull;

    float wfp[8], wdp[8], xp[12];     // prefetch registers

    auto load_chunk = [&](int c0) {
#pragma unroll
        for (int j = 0; j < 8; j++) {
            int i = tid + j * 256;             // < 2048
            int o = i >> 5, cc = i & 31;
            wfp[j] = wf[o * CIN + c0 + cc];
            wdp[j] = wd[o * CIN + c0 + cc];
        }
#pragma unroll
        for (int j = 0; j < 12; j++) {
            int i = tid + j * 256;             // < 3072
            int v = i >> 10, cc = (i >> 5) & 31, pp = i & 31;
            xp[j] = x[(size_t)(c0 + cc) * 3 * N + (size_t)v * N + (n0 + pp)];
        }
    };

    load_chunk(0);

    for (int c0 = 0; c0 < CIN; c0 += 32) {
        __syncthreads();                       // previous chunk fully consumed
        // commit prefetched chunk to smem
#pragma unroll
        for (int j = 0; j < 8; j++) {
            int i = tid + j * 256;
            int o = i >> 5, cc = i & 31;
            wsf2[cc * WS2 + o] = make_float2(wfp[j], wdp[j]);
        }
#pragma unroll
        for (int j = 0; j < 12; j++) {
            int i = tid + j * 256;
            int v = i >> 10, cc = (i >> 5) & 31, pp = i & 31;
            xsf2[(cc * 3 + v) * 32 + pp] = make_float2(xp[j], xp[j]);
        }
        __syncthreads();                       // smem ready
        if (c0 + 32 < CIN) load_chunk(c0 + 32);  // overlap with compute below

        const ulonglong2* wsv = (const ulonglong2*)ws;
#pragma unroll 4
        for (int cc = 0; cc < 32; cc++) {
            ull xv0 = xs[(cc * 3 + 0) * 32 + p];
            ull xv1 = xs[(cc * 3 + 1) * 32 + p];
            ull xv2 = xs[(cc * 3 + 2) * 32 + p];
#pragma unroll
            for (int k = 0; k < 4; k++) {
                ulonglong2 w2 = wsv[cc * (WS2 / 2) + og * 4 + k];
                int i = 2 * k;
                pd[i][0]   = f2fma(xv0, w2.x, pd[i][0]);
                pd[i][1]   = f2fma(xv1, w2.x, pd[i][1]);
                pd[i][2]   = f2fma(xv2, w2.x, pd[i][2]);
                pd[i+1][0] = f2fma(xv0, w2.y, pd[i+1][0]);
                pd[i+1][1] = f2fma(xv1, w2.y, pd[i+1][1]);
                pd[i+1][2] = f2fma(xv2, w2.y, pd[i+1][2]);
            }
        }
    }

    // nonlinearity: dot>=0 -> P ; dot<0 -> P - 0.8*(dot/(|D|^2+1e-6))*D
    float val[8][3];
#pragma unroll
    for (int i = 0; i < 8; i++) {
        float P[3], D[3];
#pragma unroll
        for (int v = 0; v < 3; v++) f2unpack(pd[i][v], P[v], D[v]);
        float dot = P[0] * D[0] + P[1] * D[1] + P[2] * D[2];
        float dd  = D[0] * D[0] + D[1] * D[1] + D[2] * D[2];
        float coef = (dot < 0.f) ? (0.8f * dot / (dd + 1e-6f)) : 0.f;
        val[i][0] = P[0] - coef * D[0];
        val[i][1] = P[1] - coef * D[1];
        val[i][2] = P[2] - coef * D[2];
    }

    if (!is2) {
#pragma unroll
        for (int i = 0; i < 8; i++) {
            int o = og * 8 + i;
#pragma unroll
            for (int v = 0; v < 3; v++)
                out[(size_t)(o * 3 + v) * N + (n0 + p)] = val[i][v];
        }
    } else {
        __syncthreads();
        float* tb = sm;                   // [32][193]
#pragma unroll
        for (int i = 0; i < 8; i++) {
            int o = og * 8 + i;
#pragma unroll
            for (int v = 0; v < 3; v++)
                tb[p * 193 + (o * 3 + v)] = val[i][v];
        }
        __syncthreads();
        for (int i = tid; i < 32 * CV; i += 256) {
            int pp = i / CV, cv = i - pp * CV;
            g_y2t[(size_t)(n0 + pp) * CV + cv] = tb[pp * 193 + cv];
        }
    }
}

// ---------------------------------------------------------------------------
// Spatial binning build (unchanged from R9): zero -> count -> prefix -> scatter
// ---------------------------------------------------------------------------
__device__ __forceinline__ int bin_of(int batch, float x, float y, float z) {
    int bx = min(G - 1, max(0, (int)(x * 8.0f)));
    int by = min(G - 1, max(0, (int)(y * 8.0f)));
    int bz = min(G - 1, max(0, (int)(z * 8.0f)));
    return batch * NBIN + (bz * G + by) * G + bx;
}

__global__ void zero_kernel() {
    int t = blockIdx.x * 256 + threadIdx.x;
    if (t < NBINT) g_cnt2[t] = 0;
    else if (t < 2 * NBINT) g_cnt1[t - NBINT] = 0;
}

__global__ void bin_count_kernel(const float* __restrict__ p1,
                                 const float* __restrict__ p2) {
    int t = blockIdx.x * 256 + threadIdx.x;
    if (t < N2TOT) {
        float x = p2[3 * t], y = p2[3 * t + 1], z = p2[3 * t + 2];
        atomicAdd(&g_cnt2[bin_of(t >> 12, x, y, z)], 1);
    } else {
        int i = t - N2TOT;
        float x = p1[3 * i], y = p1[3 * i + 1], z = p1[3 * i + 2];
        atomicAdd(&g_cnt1[bin_of(i >> 14, x, y, z)], 1);
    }
}

__global__ void prefix_kernel() {
    int* cnt   = blockIdx.x ? g_cnt1 : g_cnt2;
    int* start = blockIdx.x ? g_start1 : g_start2;
    __shared__ int wsum[8];
    int tid = threadIdx.x;
    int loc[8]; int sum = 0;
#pragma unroll
    for (int k = 0; k < 8; k++) { loc[k] = cnt[tid * 8 + k]; sum += loc[k]; }
    int lane = tid & 31, wid = tid >> 5;
    int v = sum;
#pragma unroll
    for (int o = 1; o < 32; o <<= 1) {
        int t2 = __shfl_up_sync(0xffffffffu, v, o);
        if (lane >= o) v += t2;
    }
    if (lane == 31) wsum[wid] = v;
    __syncthreads();
    int woff = 0;
    for (int k = 0; k < wid; k++) woff += wsum[k];
    int excl = woff + v - sum;
#pragma unroll
    for (int k = 0; k < 8; k++) {
        start[tid * 8 + k] = excl;
        cnt[tid * 8 + k] = excl;
        excl += loc[k];
    }
    if (tid == 255) start[NBINT] = excl;
}

__global__ void bin_scatter_kernel(const float* __restrict__ p1,
                                   const float* __restrict__ p2) {
    int t = blockIdx.x * 256 + threadIdx.x;
    if (t < N2TOT) {
        float x = p2[3 * t], y = p2[3 * t + 1], z = p2[3 * t + 2];
        int pos = atomicAdd(&g_cnt2[bin_of(t >> 12, x, y, z)], 1);
        g_b2[pos] = make_float4(x, y, z, __int_as_float(t & (N2PB - 1)));
    } else {
        int i = t - N2TOT;
        float x = p1[3 * i], y = p1[3 * i + 1], z = p1[3 * i + 2];
        int pos = atomicAdd(&g_cnt1[bin_of(i >> 14, x, y, z)], 1);
        g_b1[pos] = make_float4(x, y, z, __int_as_float(i));
    }
}

// ---------------------------------------------------------------------------
// 3-NN via bins (unchanged from R9): 3x3x3 scan + margin test + exact fallback
// ---------------------------------------------------------------------------
__global__ void __launch_bounds__(256) knn_bin_kernel()
{
    const int t = blockIdx.x * 256 + threadIdx.x;
    float4 q = g_b1[t];
    const int batch = t >> 14;
    const int orig  = __float_as_int(q.w);
    const float qx = q.x, qy = q.y, qz = q.z;
    int bx = min(G - 1, max(0, (int)(qx * 8.0f)));
    int by = min(G - 1, max(0, (int)(qy * 8.0f)));
    int bz = min(G - 1, max(0, (int)(qz * 8.0f)));

    float a0 = 3.4e38f, a1 = 3.4e38f, a2 = 3.4e38f;
    int   i0 = 0, i1 = 0, i2 = 0;

    const int xlo = max(bx - 1, 0), xhi = min(bx + 1, G - 1);
    const int ylo = max(by - 1, 0), yhi = min(by + 1, G - 1);
    const int zlo = max(bz - 1, 0), zhi = min(bz + 1, G - 1);
    const int base = batch * NBIN;

    for (int z = zlo; z <= zhi; z++) {
        for (int y = ylo; y <= yhi; y++) {
            int b0 = base + (z * G + y) * G + xlo;
            int s = g_start2[b0];
            int e = g_start2[b0 + (xhi - xlo) + 1];
            for (int j = s; j < e; j++) {
                float4 c = g_b2[j];
                float dx = qx - c.x, dy = qy - c.y, dz = qz - c.z;
                float d2 = fmaf(dx, dx, fmaf(dy, dy, dz * dz));
                int idx = __float_as_int(c.w);
                bool c0 = d2 < a0, c1 = d2 < a1, c2 = d2 < a2;
                a2 = c1 ? a1 : (c2 ? d2 : a2);  i2 = c1 ? i1 : (c2 ? idx : i2);
                a1 = c0 ? a0 : (c1 ? d2 : a1);  i1 = c0 ? i0 : (c1 ? idx : i1);
                a0 = c0 ? d2 : a0;              i0 = c0 ? idx : i0;
            }
        }
    }

    float margin = 3.4e38f;
    if (bx >= 2)     margin = fminf(margin, qx - (bx - 1) * BINW);
    if (bx <= G - 3) margin = fminf(margin, (bx + 2) * BINW - qx);
    if (by >= 2)     margin = fminf(margin, qy - (by - 1) * BINW);
    if (by <= G - 3) margin = fminf(margin, (by + 2) * BINW - qy);
    if (bz >= 2)     margin = fminf(margin, qz - (bz - 1) * BINW);
    if (bz <= G - 3) margin = fminf(margin, (bz + 2) * BINW - qz);

    if (a2 > margin * margin) {
        a0 = a1 = a2 = 3.4e38f; i0 = i1 = i2 = 0;
        int s = batch * N2PB, e = s + N2PB;
#pragma unroll 1
        for (int j = s; j < e; j++) {
            float4 c = g_b2[j];
            float dx = qx - c.x, dy = qy - c.y, dz = qz - c.z;
            float d2 = fmaf(dx, dx, fmaf(dy, dy, dz * dz));
            int idx = __float_as_int(c.w);
            bool c0 = d2 < a0, c1 = d2 < a1, c2 = d2 < a2;
            a2 = c1 ? a1 : (c2 ? d2 : a2);  i2 = c1 ? i1 : (c2 ? idx : i2);
            a1 = c0 ? a0 : (c1 ? d2 : a1);  i1 = c0 ? i0 : (c1 ? idx : i1);
            a0 = c0 ? d2 : a0;              i0 = c0 ? idx : i0;
        }
    }

    g_kd[0][orig] = a0; g_ki[0][orig] = i0;
    g_kd[1][orig] = a1; g_ki[1][orig] = i1;
    g_kd[2][orig] = a2; g_ki[2][orig] = i2;
}

// ---------------------------------------------------------------------------
// Interp weights + gather + RMW into out (coalesced over queries).
// ---------------------------------------------------------------------------
__global__ void __launch_bounds__(256) interp_kernel(float* __restrict__ out)
{
    const int ng = blockIdx.x * 256 + threadIdx.x;
    const int batch = ng >> 14;

    float a0 = g_kd[0][ng], a1 = g_kd[1][ng], a2 = g_kd[2][ng];
    int   i0 = g_ki[0][ng], i1 = g_ki[1][ng], i2 = g_ki[2][ng];

    float w0 = 1.f / (a0 + 1e-8f);
    float w1 = 1.f / (a1 + 1e-8f);
    float w2 = 1.f / (a2 + 1e-8f);
    float inv = 1.f / (w0 + w1 + w2);
    w0 *= inv; w1 *= inv; w2 *= inv;

    const float4* f0 = (const float4*)(g_y2t + (size_t)(batch * N2PB + i0) * CV);
    const float4* f1 = (const float4*)(g_y2t + (size_t)(batch * N2PB + i1) * CV);
    const float4* f2 = (const float4*)(g_y2t + (size_t)(batch * N2PB + i2) * CV);
    float* op = out + ng;

#pragma unroll 4
    for (int c4 = 0; c4 < CV / 4; c4++) {
        float4 a = f0[c4], b = f1[c4], c = f2[c4];
        op[(size_t)(4 * c4 + 0) * N1TOT] += w0 * a.x + w1 * b.x + w2 * c.x;
        op[(size_t)(4 * c4 + 1) * N1TOT] += w0 * a.y + w1 * b.y + w2 * c.y;
        op[(size_t)(4 * c4 + 2) * N1TOT] += w0 * a.z + w1 * b.z + w2 * c.z;
        op[(size_t)(4 * c4 + 3) * N1TOT] += w0 * a.w + w1 * b.w + w2 * c.w;
    }
}

// ---------------------------------------------------------------------------
extern "C" void kernel_launch(void* const* d_in, const int* in_sizes, int n_in,
                              void* d_out, int out_size)
{
    const float* p1  = (const float*)d_in[0];
    const float* x1  = (const float*)d_in[1];
    const float* p2  = (const float*)d_in[3];
    const float* x2  = (const float*)d_in[4];
    const float* w1f = (const float*)d_in[6];
    const float* w1d = (const float*)d_in[7];
    const float* w2f = (const float*)d_in[8];
    const float* w2d = (const float*)d_in[9];
    float* out = (float*)d_out;

    const int SVN = (32 * WS2 + 32 * 3 * 32) * 8;   // 41472 B

    cudaFuncSetAttribute((const void*)vn_fused_kernel,
                         cudaFuncAttributeMaxDynamicSharedMemorySize, SVN);

    // VN layers (f32x2 + prefetch pipeline): [0,512): y2 ; [512,2560): y1
    vn_fused_kernel<<<2560, 256, SVN>>>(x1, w1f, w1d, x2, w2f, w2d, out);

    // Spatial bin build (p1 and p2)
    zero_kernel<<<16, 256>>>();
    bin_count_kernel<<<(N2TOT + N1TOT) / 256, 256>>>(p1, p2);
    prefix_kernel<<<2, 256>>>();
    bin_scatter_kernel<<<(N2TOT + N1TOT) / 256, 256>>>(p1, p2);

    // 3-NN via bins (bin-sorted queries)
    knn_bin_kernel<<<N1TOT / 256, 256>>>();

    // interpolation + add into out
    interp_kernel<<<N1TOT / 256, 256>>>(out);
}